// round 17
// baseline (speedup 1.0000x reference)
#include <cuda_runtime.h>
#include <cuda_bf16.h>
#include <cstdint>

#define B      512
#define DIM    128
#define MARGIN 0.2f
#define EPSF   1e-6f
#define BIGF   1e30f
#define SENTTH 1e29f
#define FULLM  0xffffffffu

#define LDU 132    // u row stride (floats)
#define LDC 36     // Fc column stride (floats): 32 dims + 4 pad
#define LDD 516    // D slab row stride (floats)
#define NT  256    // threads per block
#define ROWS 2
#define GRID (B / ROWS)   // 256 blocks; 2 co-resident per SM

__device__ double g_num = 0.0;
__device__ unsigned long long g_den = 0ull;
__device__ unsigned int g_done = 0u;

static __device__ __forceinline__ unsigned smem_u32(const void* p) {
    return (unsigned)__cvta_generic_to_shared(p);
}
#define FMA2(acc, a, b) \
    asm volatile("fma.rn.f32x2 %0, %1, %2, %0;" : "+l"(acc) : "l"(a), "l"(b))
#define LDS_V2B64(lo, hi, addr) \
    asm volatile("ld.shared.v2.b64 {%0, %1}, [%2];" : "=l"(lo), "=l"(hi) : "r"(addr))
static __device__ __forceinline__ float hadd_f32x2(uint64_t p) {
    float lo, hi;
    asm volatile("mov.b64 {%0, %1}, %2;" : "=f"(lo), "=f"(hi) : "l"(p));
    return lo + hi;
}

// ---- 4-warp cooperative bitonic helpers (group = 128 threads, 4 keys/thread)
#define GBAR() asm volatile("bar.sync %0, 128;" :: "r"(g + 1) : "memory")

#define CMPX(a, b, ASC) {                                                     \
    const float lo = fminf(v[a], v[b]), hi = fmaxf(v[a], v[b]);               \
    v[a] = (ASC) ? lo : hi; v[b] = (ASC) ? hi : lo; }

#define SHFL_ST(JL, ASC) {                                                    \
    const bool km = (((lane & (JL)) == 0) == (ASC));                          \
    _Pragma("unroll")                                                         \
    for (int r = 0; r < 4; r++) {                                             \
        const float p = __shfl_xor_sync(FULLM, v[r], (JL));                   \
        v[r] = km ? fminf(v[r], p) : fmaxf(v[r], p);                          \
    } }

#define SMEM_ST(JT, ASC, LEAD) {                                              \
    if (LEAD) GBAR();                                                         \
    *(float4*)&D_s[g * LDD + t * 4] = make_float4(v[0], v[1], v[2], v[3]);    \
    GBAR();                                                                   \
    const float4 pv = *(const float4*)&D_s[g * LDD + (t ^ (JT)) * 4];         \
    const bool km = (((t & (JT)) == 0) == (ASC));                             \
    v[0] = km ? fminf(v[0], pv.x) : fmaxf(v[0], pv.x);                        \
    v[1] = km ? fminf(v[1], pv.y) : fmaxf(v[1], pv.y);                        \
    v[2] = km ? fminf(v[2], pv.z) : fmaxf(v[2], pv.z);                        \
    v[3] = km ? fminf(v[3], pv.w) : fmaxf(v[3], pv.w); }

// ---------------------------------------------------------------------------
// ONE fused kernel, 256 threads, 2 blocks/SM co-resident. Block b = rows
// [2b, 2b+2). Phase A: 4 d-tiles of 32 dims covering all 512 j-columns;
// thread owns columns (tid, tid+256) for both rows (2x2 micro-tile).
// Phase B: 2 groups x 4 warps cooperatively sort the 2 rows (R15-verified).
// ---------------------------------------------------------------------------
__global__ __launch_bounds__(NT, 2) void fused_kernel(const float* __restrict__ F,
                                                      const int* __restrict__ mask,
                                                      float* __restrict__ out) {
    extern __shared__ float sm[];
    float* u_s  = sm;                          //   2 * 132
    float* Fc_s = u_s + 2 * LDU;               // 512 * 36
    float* D_s  = Fc_s + B * LDC;              //   2 * 516 (also sort scratch)
    float* s_ni = D_s + 2 * LDD;               //   2
    float* s_wt = s_ni + 2;                    //   8
    int*   s_wc = (int*)(s_wt + 8);            //   8
    int*   s_np = s_wc + 8;                    //   8
    int*   s_nn = s_np + 8;                    //   8
    float* s_bs = (float*)(s_nn + 8);          //   8

    const int tid  = threadIdx.x;
    const int lane = tid & 31;
    const int warp = tid >> 5;
    const int i0   = blockIdx.x * ROWS;
    const int g    = warp >> 2;       // sort group = row (0..1)
    const int wg   = warp & 3;        // warp within group
    const int t    = wg * 32 + lane;  // thread index within group

    // ---- prefetch mask quad for my sort elements -----------------------------
    const int4 m4 = ((const int4*)(mask + (i0 + g) * B))[t];

    // ---- stage u = f(anchor rows) + eps (1 elem/thread, 256 = 2*128) --------
    {
        const int r = tid >> 7, d = tid & 127;
        u_s[r * LDU + d] = F[(i0 + r) * DIM + d] + EPSF;
    }
    __syncthreads();

    // ---- |u_i|^2 (warps 0-1; warp w -> row w) --------------------------------
    if (warp < ROWS) {
        float s = 0.f;
#pragma unroll
        for (int qq = 0; qq < 4; qq++) {
            const float x = u_s[warp * LDU + lane + 32 * qq];
            s = fmaf(x, x, s);
        }
#pragma unroll
        for (int off = 16; off; off >>= 1) s += __shfl_down_sync(FULLM, s, off);
        if (lane == 0) s_ni[warp] = s;
    }

    const float4* F4 = (const float4*)F;
    const unsigned ub  = smem_u32(u_s);
    const unsigned fb0 = smem_u32(Fc_s) + (unsigned)tid * LDC * 4u;
    const unsigned fb1 = smem_u32(Fc_s) + (unsigned)(tid + 256) * LDC * 4u;

    // ---- Phase A: 4 d-tiles of 32 dims, all 512 columns ----------------------
    uint64_t A00 = 0ull, A01 = 0ull, A10 = 0ull, A11 = 0ull;
    uint64_t NF0 = 0ull, NF1 = 0ull;

#pragma unroll
    for (int c = 0; c < 4; c++) {
        if (c) __syncthreads();    // protect Fc_s reuse across d-tiles
        // stage: 512 rows x 8 float4 (dims [32c, 32c+32)), 16 per thread
#pragma unroll
        for (int k = 0; k < 16; k++) {
            const int gidx = tid + (k << 8);
            const int row = gidx >> 3, sub = gidx & 7;
            const float4 fv = F4[row * 32 + c * 8 + sub];
            *(float4*)&Fc_s[row * LDC + sub * 4] = fv;
        }
        __syncthreads();

        const unsigned u0a = ub + (0 * LDU + 32 * c) * 4u;
        const unsigned u1a = ub + (1 * LDU + 32 * c) * 4u;
#pragma unroll
        for (int dq = 0; dq < 8; dq++) {
            uint64_t f0, f1, g0, g1, x0, x1, y0, y1;
            LDS_V2B64(f0, f1, fb0 + 16 * dq);
            LDS_V2B64(g0, g1, fb1 + 16 * dq);
            LDS_V2B64(x0, x1, u0a + 16 * dq);
            LDS_V2B64(y0, y1, u1a + 16 * dq);
            FMA2(NF0, f0, f0);  FMA2(NF0, f1, f1);
            FMA2(NF1, g0, g0);  FMA2(NF1, g1, g1);
            FMA2(A00, x0, f0);  FMA2(A00, x1, f1);
            FMA2(A01, x0, g0);  FMA2(A01, x1, g1);
            FMA2(A10, y0, f0);  FMA2(A10, y1, f1);
            FMA2(A11, y0, g0);  FMA2(A11, y1, g1);
        }
    }

    // ---- epilogue: D slab (thread owns columns tid, tid+256) -----------------
    {
        const float a00 = hadd_f32x2(A00);
        const float a01 = hadd_f32x2(A01);
        const float a10 = hadd_f32x2(A10);
        const float a11 = hadd_f32x2(A11);
        const float nf0 = hadd_f32x2(NF0);
        const float nf1 = hadd_f32x2(NF1);
        const float n0 = s_ni[0], n1 = s_ni[1];
        D_s[0 * LDD + tid]       = sqrtf(fmaxf(n0 + nf0 - 2.f * a00, 0.f));
        D_s[0 * LDD + tid + 256] = sqrtf(fmaxf(n0 + nf1 - 2.f * a01, 0.f));
        D_s[1 * LDD + tid]       = sqrtf(fmaxf(n1 + nf0 - 2.f * a10, 0.f));
        D_s[1 * LDD + tid + 256] = sqrtf(fmaxf(n1 + nf1 - 2.f * a11, 0.f));
    }
    __syncthreads();   // D_s complete

    // =========================================================================
    // Phase B: 2 groups x 4 warps; group g sorts row i0+g cooperatively.
    // Thread owns elements e = t*4 + r. LSB tag; sentinel value-guarded.
    // (Verified R15/R16.)
    // =========================================================================
    float v[4];
    int npos = 0, nneg = 0;
    {
        const float4 d4 = *(const float4*)&D_s[g * LDD + t * 4];
        const float dv[4] = {d4.x, d4.y, d4.z, d4.w};
        const int   mv[4] = {m4.x, m4.y, m4.z, m4.w};
        const int   i     = i0 + g;
#pragma unroll
        for (int r = 0; r < 4; r++) {
            const int j = t * 4 + r;
            unsigned kb;
            if (mv[r] != 0) {
                kb = __float_as_uint(dv[r] + MARGIN) | 1u;
                npos++;
            } else if (j == i) {
                kb = __float_as_uint(BIGF) & ~1u;
            } else {
                kb = __float_as_uint(dv[r]) & ~1u;
                nneg++;
            }
            v[r] = __uint_as_float(kb);
        }
    }

    // ---- cooperative bitonic sort, ascending over e = t*4 + r ---------------
    {
        // k = 2
        CMPX(0, 1, true)  CMPX(2, 3, false)
        // k = 4
        { const bool A = ((lane & 1) == 0);
          CMPX(0, 2, A) CMPX(1, 3, A) CMPX(0, 1, A) CMPX(2, 3, A) }
        // k = 8
        { const bool A = ((lane & 2) == 0);
          SHFL_ST(1, A)
          CMPX(0, 2, A) CMPX(1, 3, A) CMPX(0, 1, A) CMPX(2, 3, A) }
        // k = 16
        { const bool A = ((lane & 4) == 0);
          SHFL_ST(2, A) SHFL_ST(1, A)
          CMPX(0, 2, A) CMPX(1, 3, A) CMPX(0, 1, A) CMPX(2, 3, A) }
        // k = 32
        { const bool A = ((lane & 8) == 0);
          SHFL_ST(4, A) SHFL_ST(2, A) SHFL_ST(1, A)
          CMPX(0, 2, A) CMPX(1, 3, A) CMPX(0, 1, A) CMPX(2, 3, A) }
        // k = 64
        { const bool A = ((lane & 16) == 0);
          SHFL_ST(8, A) SHFL_ST(4, A) SHFL_ST(2, A) SHFL_ST(1, A)
          CMPX(0, 2, A) CMPX(1, 3, A) CMPX(0, 1, A) CMPX(2, 3, A) }
        // k = 128
        { const bool A = ((wg & 1) == 0);
          SHFL_ST(16, A) SHFL_ST(8, A) SHFL_ST(4, A) SHFL_ST(2, A) SHFL_ST(1, A)
          CMPX(0, 2, A) CMPX(1, 3, A) CMPX(0, 1, A) CMPX(2, 3, A) }
        // k = 256
        { const bool A = ((wg & 2) == 0);
          SMEM_ST(32, A, 0)
          SHFL_ST(16, A) SHFL_ST(8, A) SHFL_ST(4, A) SHFL_ST(2, A) SHFL_ST(1, A)
          CMPX(0, 2, A) CMPX(1, 3, A) CMPX(0, 1, A) CMPX(2, 3, A) }
        // k = 512 (ascending everywhere)
        {
          SMEM_ST(64, true, 1)
          SMEM_ST(32, true, 1)
          SHFL_ST(16, true) SHFL_ST(8, true) SHFL_ST(4, true)
          SHFL_ST(2, true)  SHFL_ST(1, true)
          CMPX(0, 2, true) CMPX(1, 3, true) CMPX(0, 1, true) CMPX(2, 3, true)
        }
    }

    // ---- pass 1: negative (sum, count) scan across the group -----------------
    float runs = 0.f;
    int   runc = 0;
#pragma unroll
    for (int r = 0; r < 4; r++) {
        const bool isneg = ((__float_as_uint(v[r]) & 1u) == 0) && (v[r] < SENTTH);
        if (isneg) { runs += v[r]; runc++; }
    }
    float ls = runs;
    int   lc = runc;
#pragma unroll
    for (int off = 1; off < 32; off <<= 1) {
        const float y = __shfl_up_sync(FULLM, ls, off);
        const int   z = __shfl_up_sync(FULLM, lc, off);
        if (lane >= off) { ls += y; lc += z; }
    }
    {
        const float wts = __shfl_sync(FULLM, ls, 31);
        const int   wtc = __shfl_sync(FULLM, lc, 31);
        const int wnp = __reduce_add_sync(FULLM, npos);
        const int wnn = __reduce_add_sync(FULLM, nneg);
        if (lane == 0) {
            s_wt[g * 4 + wg] = wts;
            s_wc[g * 4 + wg] = wtc;
            s_np[g * 4 + wg] = wnp;
            s_nn[g * 4 + wg] = wnn;
        }
    }
    GBAR();
    float gs = 0.f;
    int   gc = 0;
#pragma unroll
    for (int w = 0; w < 4; w++) {
        if (w < wg) { gs += s_wt[g * 4 + w]; gc += s_wc[g * 4 + w]; }
    }
    float rs = gs + (ls - runs);
    int   rc = gc + (lc - runc);

    // ---- pass 2: positive contributions along sorted order -------------------
    float local = 0.f;
#pragma unroll
    for (int r = 0; r < 4; r++) {
        const bool ispos = (__float_as_uint(v[r]) & 1u) != 0;
        if (ispos) {
            local += (float)rc * v[r] - rs;
        } else if (v[r] < SENTTH) {
            rs += v[r];
            rc++;
        }
    }
#pragma unroll
    for (int off = 16; off; off >>= 1)
        local += __shfl_down_sync(FULLM, local, off);
    if (lane == 0) s_bs[g * 4 + wg] = local;
    __syncthreads();

    if (tid == 0) {
        float s = 0.f;
        unsigned long long d = 0ull;
#pragma unroll
        for (int gg = 0; gg < ROWS; gg++) {
            int np = 0, nn = 0;
#pragma unroll
            for (int w = 0; w < 4; w++) {
                s  += s_bs[gg * 4 + w];
                np += s_np[gg * 4 + w];
                nn += s_nn[gg * 4 + w];
            }
            d += (unsigned long long)np * (unsigned long long)nn;
        }
        atomicAdd(&g_num, (double)s);
        atomicAdd(&g_den, d);
        __threadfence();
        const unsigned int ticket = atomicAdd(&g_done, 1u);
        if (ticket == gridDim.x - 1) {
            const double num = atomicAdd(&g_num, 0.0);
            const unsigned long long den = atomicAdd(&g_den, 0ull);
            out[0] = (den > 0ull) ? (float)(num / (double)den) : 0.0f;
            g_num  = 0.0;
            g_den  = 0ull;
            __threadfence();
            g_done = 0u;
        }
    }
}

// ---------------------------------------------------------------------------
extern "C" void kernel_launch(void* const* d_in, const int* in_sizes, int n_in,
                              void* d_out, int out_size) {
    const float* features = (const float*)d_in[0];   // [512,128] f32
    const int*   mask     = (const int*)d_in[1];     // [512,512] i32
    float* out = (float*)d_out;

    const int smem_bytes =
        (2 * LDU + B * LDC + 2 * LDD + 2 + 8 + 8) * (int)sizeof(float)
        + (8 + 8 + 8) * (int)sizeof(int);
    static bool attr_set = false;
    if (!attr_set) {
        cudaFuncSetAttribute(fused_kernel, cudaFuncAttributeMaxDynamicSharedMemorySize,
                             smem_bytes);
        attr_set = true;
    }

    fused_kernel<<<GRID, NT, smem_bytes>>>(features, mask, out);
}